// round 1
// baseline (speedup 1.0000x reference)
#include <cuda_runtime.h>
#include <cstdint>

// Problem constants
#define N_PIX   16384      // 16 * 32 * 32 pixels
#define N_CODES 16384
#define DIM     256
#define HW      1024       // 32*32 per batch image

// Tiling
#define BM 64              // pixels per block
#define BN 128             // codes per code-tile
#define BK 32              // K chunk held in smem
#define TM 4               // pixels per thread
#define TN 8               // codes per thread
#define NTHREADS 256       // 16 x 16

#define BNP (BN + 4)       // padded Es row

// Output layout (floats): [z_q 4194304][loss 1][indices 16384]
#define ZQ_ELEMS  (16 * DIM * HW)
#define LOSS_OFF  ZQ_ELEMS
#define IDX_OFF   (ZQ_ELEMS + 1)

// Scratch: per-code squared norms
__device__ float g_enorm[N_CODES];

// ---------------------------------------------------------------------------
// Kernel 1: ||e||^2 per code. One warp per code, float4 loads.
// ---------------------------------------------------------------------------
__global__ void enorm_kernel(const float* __restrict__ emb) {
    int code = blockIdx.x * 8 + (threadIdx.x >> 5);
    int lane = threadIdx.x & 31;
    const float4* row = reinterpret_cast<const float4*>(emb + (size_t)code * DIM);
    float s = 0.f;
#pragma unroll
    for (int i = 0; i < 2; i++) {
        float4 v = row[lane + 32 * i];
        s += v.x * v.x + v.y * v.y + v.z * v.z + v.w * v.w;
    }
#pragma unroll
    for (int o = 16; o > 0; o >>= 1) s += __shfl_xor_sync(0xffffffffu, s, o);
    if (lane == 0) g_enorm[code] = s;
}

// ---------------------------------------------------------------------------
// Kernel 2: fused GEMM + argmin + gather write.
// Each block owns BM=64 pixels (one contiguous hw-run within one batch image,
// since 64 | 1024). Z panel [DIM][BM] stays resident in smem; iterate over all
// code tiles of BN=128, accumulating a running per-pixel argmin of
// d = ||e||^2 - 2 * (z . e).
// ---------------------------------------------------------------------------
__global__ void __launch_bounds__(NTHREADS, 2)
vq_kernel(const float* __restrict__ z, const float* __restrict__ emb,
          float* __restrict__ out) {
    extern __shared__ float smem[];
    float* Zs   = smem;                      // [DIM][BM]           16384 f
    float* Es   = Zs + DIM * BM;             // [BK][BNP]           4224 f
    float* redV = Es + BK * BNP;             // [BM][16]            1024 f
    int*   redI = reinterpret_cast<int*>(redV + BM * 16); // [BM][16] 1024 i
    __shared__ int finalIdx[BM];

    const int tid = threadIdx.x;
    const int tx = tid & 15;                 // code group
    const int ty = tid >> 4;                 // pixel group

    const int p0  = blockIdx.x * BM;
    const int b   = p0 >> 10;                // batch image
    const int hw0 = p0 & (HW - 1);
    const float* zb = z + ((size_t)b * DIM) * HW + hw0;

    // Load Z panel: Zs[d][px] = z[b][d][hw0+px]  (coalesced 256B rows)
    for (int i = tid; i < DIM * BM; i += NTHREADS) {
        int d = i >> 6, px = i & 63;
        Zs[d * BM + px] = zb[(size_t)d * HW + px];
    }
    __syncthreads();

    float bestV[TM];
    int   bestI[TM];
#pragma unroll
    for (int i = 0; i < TM; i++) { bestV[i] = 3.4e38f; bestI[i] = 0; }

    for (int ct = 0; ct < N_CODES / BN; ct++) {
        const int n0 = ct * BN;
        float acc[TM][TN];
#pragma unroll
        for (int i = 0; i < TM; i++)
#pragma unroll
            for (int j = 0; j < TN; j++) acc[i][j] = 0.f;

#pragma unroll 1
        for (int kc = 0; kc < DIM / BK; kc++) {
            __syncthreads();
            // Load E chunk [BK d][BN codes], transposed into Es[d][code].
            {
                int j = tid >> 1;            // code within tile
                int h = tid & 1;             // half of the 32-float k-row
                const float4* src = reinterpret_cast<const float4*>(
                    emb + ((size_t)(n0 + j)) * DIM + kc * BK) + h * 4;
#pragma unroll
                for (int q = 0; q < 4; q++) {
                    float4 v = src[q];
                    int dd = h * 16 + q * 4;
                    Es[(dd + 0) * BNP + j] = v.x;
                    Es[(dd + 1) * BNP + j] = v.y;
                    Es[(dd + 2) * BNP + j] = v.z;
                    Es[(dd + 3) * BNP + j] = v.w;
                }
            }
            __syncthreads();

#pragma unroll
            for (int d = 0; d < BK; d++) {
                float4 zv = *reinterpret_cast<const float4*>(
                    &Zs[(kc * BK + d) * BM + ty * TM]);
                float4 e0 = *reinterpret_cast<const float4*>(
                    &Es[d * BNP + tx * TN]);
                float4 e1 = *reinterpret_cast<const float4*>(
                    &Es[d * BNP + tx * TN + 4]);
                float zz[TM] = {zv.x, zv.y, zv.z, zv.w};
                float ee[TN] = {e0.x, e0.y, e0.z, e0.w, e1.x, e1.y, e1.z, e1.w};
#pragma unroll
                for (int i = 0; i < TM; i++)
#pragma unroll
                    for (int j = 0; j < TN; j++)
                        acc[i][j] += zz[i] * ee[j];
            }
        }

        // Fold this code tile into the running argmin.
#pragma unroll
        for (int j = 0; j < TN; j++) {
            int code = n0 + tx * TN + j;
            float en = __ldg(&g_enorm[code]);
#pragma unroll
            for (int i = 0; i < TM; i++) {
                float dv = en - 2.f * acc[i][j];
                if (dv < bestV[i]) { bestV[i] = dv; bestI[i] = code; }
            }
        }
    }

    // Cross-thread (tx) reduction per pixel; smaller index wins ties.
    __syncthreads();
#pragma unroll
    for (int i = 0; i < TM; i++) {
        redV[(ty * TM + i) * 16 + tx] = bestV[i];
        redI[(ty * TM + i) * 16 + tx] = bestI[i];
    }
    __syncthreads();
    if (tid < BM) {
        float bv = redV[tid * 16];
        int   bi = redI[tid * 16];
#pragma unroll
        for (int t = 1; t < 16; t++) {
            float v = redV[tid * 16 + t];
            int   ii = redI[tid * 16 + t];
            if (v < bv || (v == bv && ii < bi)) { bv = v; bi = ii; }
        }
        finalIdx[tid] = bi;
        out[IDX_OFF + p0 + tid] = (float)bi;   // indices as float
    }
    __syncthreads();

    // z_q_out in NCHW: out[(b*DIM + d)*HW + hw0 + px] = emb[idx[px]*DIM + d]
    for (int i = tid; i < DIM * BM; i += NTHREADS) {
        int d = i >> 6, px = i & 63;
        out[((size_t)b * DIM + d) * HW + hw0 + px] =
            emb[(size_t)finalIdx[px] * DIM + d];
    }

    if (blockIdx.x == 0 && tid == 0) out[LOSS_OFF] = 0.f;
}

// ---------------------------------------------------------------------------
extern "C" void kernel_launch(void* const* d_in, const int* in_sizes, int n_in,
                              void* d_out, int out_size) {
    const float* z   = (const float*)d_in[0];      // (16,256,32,32) f32
    const float* emb = (const float*)d_in[1];      // (16384,256)    f32
    float* out = (float*)d_out;

    (void)in_sizes; (void)n_in; (void)out_size;

    // Opt-in smem size for the main kernel (~88.5 KB dynamic).
    static bool attr_set = false;
    size_t smem_bytes = (size_t)(DIM * BM + BK * BNP + BM * 16) * sizeof(float)
                      + (size_t)(BM * 16) * sizeof(int);
    if (!attr_set) {
        cudaFuncSetAttribute(vq_kernel,
                             cudaFuncAttributeMaxDynamicSharedMemorySize,
                             (int)smem_bytes);
        attr_set = true;
    }

    enorm_kernel<<<N_CODES / 8, 256>>>(emb);
    vq_kernel<<<N_PIX / BM, NTHREADS, smem_bytes>>>(z, emb, out);
}

// round 3
// speedup vs baseline: 2.9721x; 2.9721x over previous
#include <cuda_runtime.h>
#include <cstdint>

#define N_PIX   16384
#define N_CODES 16384
#define DIM     256
#define HW      1024

#define KE      288        // 256 tf32 dims + 32-col norm block
#define ASTRIDE 292        // A smem row stride (floats), conflict-free
#define BSTRIDE 36         // B smem row stride (floats)
#define KC      32         // K per pipeline chunk
#define NCH     9          // chunks per code tile (288/32)
#define PX_CTA  64         // pixels per CTA
#define NTILE   128        // codes per tile iteration
#define NTILES  (N_CODES / NTILE)      // 128
#define NCHUNKS (NTILES * NCH)         // 1152
#define GT      256        // gemm threads (8 warps: 2M x 4N)

#define A_FLOATS (PX_CTA * ASTRIDE)            // 18688
#define B_STAGE_FLOATS (NTILE * BSTRIDE)       // 4608
#define DYN_FLOATS (A_FLOATS + 2 * B_STAGE_FLOATS)   // 27904 -> 111616 B

#define ZQ_ELEMS (16 * DIM * HW)
#define LOSS_OFF ZQ_ELEMS
#define IDX_OFF  (ZQ_ELEMS + 1)

// device scratch
__device__ float g_Zt[(size_t)N_PIX * KE];     // tf32(z) + [1,1,1,0..]
__device__ float g_Zte[(size_t)N_PIX * DIM];   // exact transposed z
__device__ float g_E[(size_t)N_CODES * KE];    // tf32(e) + [-n/2 splits,0..]
__device__ float g_norm2[N_CODES];             // exact ||e||^2
__device__ int2  g_top2[N_PIX];                // approx top-2 candidates

__device__ __forceinline__ float tf32r(float x) {
    float r; asm("cvt.rna.tf32.f32 %0, %1;" : "=f"(r) : "f"(x)); return r;
}
__device__ __forceinline__ void cpasync16(void* dst_smem, const float* src) {
    uint32_t d = (uint32_t)__cvta_generic_to_shared(dst_smem);
    asm volatile("cp.async.cg.shared.global [%0], [%1], 16;" :: "r"(d), "l"(src));
}
__device__ __forceinline__ void mma1688(float* c, const uint32_t* a,
                                        const uint32_t* b) {
    asm volatile(
        "mma.sync.aligned.m16n8k8.row.col.f32.tf32.tf32.f32 "
        "{%0,%1,%2,%3},{%4,%5,%6,%7},{%8,%9},{%0,%1,%2,%3};"
        : "+f"(c[0]), "+f"(c[1]), "+f"(c[2]), "+f"(c[3])
        : "r"(a[0]), "r"(a[1]), "r"(a[2]), "r"(a[3]), "r"(b[0]), "r"(b[1]));
}

// ---------------------------------------------------------------------------
// Prep E: tf32-rounded rows + norm block; exact ||e||^2. One warp per code.
// ---------------------------------------------------------------------------
__global__ void prep_e_kernel(const float* __restrict__ emb) {
    int code = blockIdx.x * 8 + (threadIdx.x >> 5);
    int lane = threadIdx.x & 31;
    const float* src = emb + (size_t)code * DIM + lane * 8;
    float* row = g_E + (size_t)code * KE;

    float en = 0.f;
#pragma unroll
    for (int t = 0; t < 8; t++) {
        float v = src[t];
        en += v * v;
        row[lane * 8 + t] = tf32r(v);
    }
#pragma unroll
    for (int o = 16; o > 0; o >>= 1) en += __shfl_xor_sync(0xffffffffu, en, o);
    if (lane == 0) g_norm2[code] = en;

    float t0 = -0.5f * en;
    float nh = tf32r(t0);
    float nm = tf32r(t0 - nh);
    float nl = tf32r(t0 - nh - nm);
    nh = __shfl_sync(0xffffffffu, nh, 0);
    nm = __shfl_sync(0xffffffffu, nm, 0);
    nl = __shfl_sync(0xffffffffu, nl, 0);
    row[256 + lane] = (lane == 0) ? nh : (lane == 1) ? nm : (lane == 2) ? nl : 0.f;
}

// ---------------------------------------------------------------------------
// Prep Z: transpose NCHW -> pixel-major; tf32 copy + ones block + exact copy.
// ---------------------------------------------------------------------------
__global__ void prep_z_kernel(const float* __restrict__ z) {
    __shared__ float Zs[DIM][33];
    int tid = threadIdx.x;
    int lane = tid & 31;
    int wid = tid >> 5;
    int px0 = blockIdx.x * 32;
    int b = px0 >> 10;
    int hw0 = px0 & (HW - 1);

    for (int i = tid; i < DIM * 32; i += 256) {
        int d = i >> 5, px = i & 31;
        Zs[d][px] = z[((size_t)b * DIM + d) * HW + hw0 + px];
    }
    __syncthreads();

#pragma unroll
    for (int pp = 0; pp < 4; pp++) {
        int px = wid + pp * 8;
        float* rowT = g_Zt + (size_t)(px0 + px) * KE;
        float* rowE = g_Zte + (size_t)(px0 + px) * DIM;
#pragma unroll
        for (int i = 0; i < 8; i++) {
            int d = lane + 32 * i;
            float v = Zs[d][px];
            rowT[d] = tf32r(v);
            rowE[d] = v;
        }
        rowT[256 + lane] = (lane < 3) ? 1.0f : 0.f;
    }
}

// ---------------------------------------------------------------------------
// Main GEMM: per CTA 64 pixels, iterate 128 code tiles; top-2 argmax fold.
// ---------------------------------------------------------------------------
__global__ void __launch_bounds__(GT, 2)
vq_gemm_kernel() {
    extern __shared__ float dsm[];
    float* As = dsm;                       // [64][292]
    float* Bs = dsm + A_FLOATS;            // 2 stages of [128][36]

    const int tid = threadIdx.x;
    const int lane = tid & 31;
    const int wid = tid >> 5;
    const int mw = wid >> 2;               // 0..1
    const int nw = wid & 3;                // 0..3
    const int lr = lane >> 2;              // 0..7
    const int lc = lane & 3;               // 0..3
    const int p0 = blockIdx.x * PX_CTA;

    // ---- preload A panel (full K) + first B chunk ----
    {
        const float* gz = g_Zt + (size_t)p0 * KE;
        for (int id = tid; id < PX_CTA * (KE / 4); id += GT) {
            int row = id / (KE / 4), q = id % (KE / 4);
            cpasync16(&As[row * ASTRIDE + q * 4], gz + (size_t)row * KE + q * 4);
        }
        const float* ge = g_E;  // tile 0, chunk 0
#pragma unroll
        for (int j = 0; j < 4; j++) {
            int id = tid * 4 + j;
            int n = id >> 3, q = id & 7;
            cpasync16(&Bs[n * BSTRIDE + q * 4], ge + (size_t)n * KE + q * 4);
        }
        asm volatile("cp.async.commit_group;" ::: "memory");
    }

    float acc[2][4][4];
    float v1[4], v2[4];
    int i1[4], i2[4];
#pragma unroll
    for (int s = 0; s < 4; s++) {
        v1[s] = -3.4e38f; v2[s] = -3.4e38f; i1[s] = 0; i2[s] = 1;
    }
#pragma unroll
    for (int mt = 0; mt < 2; mt++)
#pragma unroll
        for (int nt = 0; nt < 4; nt++)
#pragma unroll
            for (int r = 0; r < 4; r++) acc[mt][nt][r] = 0.f;

    const float* aBase = As + (mw * 32 + lr) * ASTRIDE + lc;

    int t_cur = 0, c_cur = 0;    // chunk being computed
    int t_nxt = 0, c_nxt = 1;    // next chunk to load

    for (int cc = 0; cc < NCHUNKS; cc++) {
        // issue next chunk
        if (cc + 1 < NCHUNKS) {
            float* bs = Bs + ((cc + 1) & 1) * B_STAGE_FLOATS;
            const float* ge = g_E + (size_t)t_nxt * NTILE * KE + c_nxt * KC;
#pragma unroll
            for (int j = 0; j < 4; j++) {
                int id = tid * 4 + j;
                int n = id >> 3, q = id & 7;
                cpasync16(&bs[n * BSTRIDE + q * 4], ge + (size_t)n * KE + q * 4);
            }
            if (++c_nxt == NCH) { c_nxt = 0; t_nxt++; }
        }
        asm volatile("cp.async.commit_group;" ::: "memory");
        asm volatile("cp.async.wait_group 1;" ::: "memory");
        __syncthreads();

        // compute current chunk: 4 k8 steps
        const float* bs = Bs + (cc & 1) * B_STAGE_FLOATS;
        const float* bBase = bs + (nw * 32 + lr) * BSTRIDE + lc;
        const int kb0 = c_cur * KC;
#pragma unroll
        for (int k8 = 0; k8 < 4; k8++) {
            const int kb = kb0 + k8 * 8;
            uint32_t a[2][4];
#pragma unroll
            for (int mt = 0; mt < 2; mt++) {
                const float* ap = aBase + mt * 16 * ASTRIDE + kb;
                a[mt][0] = __float_as_uint(ap[0]);
                a[mt][1] = __float_as_uint(ap[8 * ASTRIDE]);
                a[mt][2] = __float_as_uint(ap[4]);
                a[mt][3] = __float_as_uint(ap[8 * ASTRIDE + 4]);
            }
            uint32_t b[4][2];
#pragma unroll
            for (int nt = 0; nt < 4; nt++) {
                const float* bp = bBase + nt * 8 * BSTRIDE + k8 * 8;
                b[nt][0] = __float_as_uint(bp[0]);
                b[nt][1] = __float_as_uint(bp[4]);
            }
#pragma unroll
            for (int mt = 0; mt < 2; mt++)
#pragma unroll
                for (int nt = 0; nt < 4; nt++)
                    mma1688(acc[mt][nt], a[mt], b[nt]);
        }
        __syncthreads();

        // end of a code tile -> fold top-2 and reset accumulators
        if (++c_cur == NCH) {
            const int cbase = t_cur * NTILE + nw * 32 + lc * 2;
#pragma unroll
            for (int mt = 0; mt < 2; mt++)
#pragma unroll
                for (int nt = 0; nt < 4; nt++)
#pragma unroll
                    for (int r = 0; r < 4; r++) {
                        float v = acc[mt][nt][r];
                        int slot = mt * 2 + (r >> 1);
                        int code = cbase + nt * 8 + (r & 1);
                        if (v > v1[slot]) {
                            v2[slot] = v1[slot]; i2[slot] = i1[slot];
                            v1[slot] = v; i1[slot] = code;
                        } else if (v > v2[slot]) {
                            v2[slot] = v; i2[slot] = code;
                        }
                        acc[mt][nt][r] = 0.f;
                    }
            c_cur = 0; t_cur++;
        }
    }

    // ---- cross-thread top-2 reduce (reuse B smem region) ----
    __syncthreads();
    float4* red = (float4*)Bs;  // [64 px][16 contrib]
    const int contrib = nw * 4 + lc;
#pragma unroll
    for (int slot = 0; slot < 4; slot++) {
        int mt = slot >> 1, rh = slot & 1;
        int pxl = mw * 32 + mt * 16 + rh * 8 + lr;
        red[pxl * 16 + contrib] =
            make_float4(v1[slot], __int_as_float(i1[slot]),
                        v2[slot], __int_as_float(i2[slot]));
    }
    __syncthreads();
    if (tid < PX_CTA) {
        float bv1 = -3.4e38f, bv2 = -3.4e38f;
        int bi1 = 0, bi2 = 1;
#pragma unroll
        for (int c = 0; c < 16; c++) {
            float4 e = red[tid * 16 + c];
#pragma unroll
            for (int h = 0; h < 2; h++) {
                float v = h ? e.z : e.x;
                int idx = __float_as_int(h ? e.w : e.y);
                if (v > bv1 || (v == bv1 && idx < bi1)) {
                    bv2 = bv1; bi2 = bi1; bv1 = v; bi1 = idx;
                } else if (v > bv2) {
                    bv2 = v; bi2 = idx;
                }
            }
        }
        g_top2[p0 + tid] = make_int2(bi1, bi2);
    }
}

// ---------------------------------------------------------------------------
// Exact rescore of top-2 + gather + outputs.
// ---------------------------------------------------------------------------
__global__ void __launch_bounds__(256)
rescore_gather_kernel(const float* __restrict__ emb, float* __restrict__ out) {
    __shared__ int sel[PX_CTA];
    const int tid = threadIdx.x;
    const int lane = tid & 31;
    const int wid = tid >> 5;
    const int p0 = blockIdx.x * PX_CTA;

#pragma unroll 1
    for (int j = 0; j < 8; j++) {
        const int pxl = wid * 8 + j;
        const int px = p0 + pxl;
        const int2 cand = g_top2[px];
        const float4* zp = (const float4*)(g_Zte + (size_t)px * DIM);
        const float4* e1 = (const float4*)(emb + (size_t)cand.x * DIM);
        const float4* e2 = (const float4*)(emb + (size_t)cand.y * DIM);
        float d1 = 0.f, d2 = 0.f;
#pragma unroll
        for (int t = 0; t < 2; t++) {
            float4 zv = zp[lane + 32 * t];
            float4 a = e1[lane + 32 * t];
            float4 b = e2[lane + 32 * t];
            d1 += zv.x * a.x + zv.y * a.y + zv.z * a.z + zv.w * a.w;
            d2 += zv.x * b.x + zv.y * b.y + zv.z * b.z + zv.w * b.w;
        }
#pragma unroll
        for (int o = 16; o > 0; o >>= 1) {
            d1 += __shfl_xor_sync(0xffffffffu, d1, o);
            d2 += __shfl_xor_sync(0xffffffffu, d2, o);
        }
        if (lane == 0) {
            float s1 = d1 - 0.5f * g_norm2[cand.x];
            float s2 = d2 - 0.5f * g_norm2[cand.y];
            int best;
            if (s1 > s2) best = cand.x;
            else if (s2 > s1) best = cand.y;
            else best = min(cand.x, cand.y);
            sel[pxl] = best;
            out[IDX_OFF + px] = (float)best;
        }
    }
    __syncthreads();

    const int b = p0 >> 10;
    const int hw0 = p0 & (HW - 1);
    for (int i = tid; i < DIM * PX_CTA; i += 256) {
        int d = i >> 6, pxl = i & 63;
        out[((size_t)b * DIM + d) * HW + hw0 + pxl] =
            emb[(size_t)sel[pxl] * DIM + d];
    }
    if (blockIdx.x == 0 && tid == 0) out[LOSS_OFF] = 0.f;
}

// ---------------------------------------------------------------------------
extern "C" void kernel_launch(void* const* d_in, const int* in_sizes, int n_in,
                              void* d_out, int out_size) {
    const float* z = (const float*)d_in[0];
    const float* emb = (const float*)d_in[1];
    float* out = (float*)d_out;
    (void)in_sizes; (void)n_in; (void)out_size;

    static bool attr_set = false;
    if (!attr_set) {
        cudaFuncSetAttribute(vq_gemm_kernel,
                             cudaFuncAttributeMaxDynamicSharedMemorySize,
                             DYN_FLOATS * (int)sizeof(float));
        attr_set = true;
    }

    prep_z_kernel<<<N_PIX / 32, 256>>>(z);
    prep_e_kernel<<<N_CODES / 8, 256>>>(emb);
    vq_gemm_kernel<<<N_PIX / PX_CTA, GT, DYN_FLOATS * sizeof(float)>>>();
    rescore_gather_kernel<<<N_PIX / PX_CTA, 256>>>(emb, out);
}

// round 5
// speedup vs baseline: 6.0216x; 2.0261x over previous
#include <cuda_runtime.h>
#include <cuda_fp16.h>
#include <cstdint>

#define N_PIX   16384
#define N_CODES 16384
#define DIM     256
#define HW      1024

#define PX_CTA  64
#define NTILE   256
#define NTILES  (N_CODES / NTILE)   // 64
#define KC      64
#define NCH     (DIM / KC)          // 4 chunks per tile
#define NCHUNKS (NTILES * NCH)      // 256
#define GT      256                 // 8 warps: 2M x 4N, warp tile 32x64

#define ASTR    264                 // A smem row stride (f16)
#define BSTR    72                  // B smem row stride (f16)
#define A_BYTES      (PX_CTA * ASTR * 2)   // 33792
#define BSTAGE_BYTES (NTILE * BSTR * 2)    // 36864
#define NS_OFF  (A_BYTES + 2 * BSTAGE_BYTES)
#define DYN_BYTES (NS_OFF + 2 * NTILE * 4) // 111616

#define ZQ_ELEMS (16 * DIM * HW)
#define LOSS_OFF ZQ_ELEMS
#define IDX_OFF  (ZQ_ELEMS + 1)

__device__ __half g_Zh[(size_t)N_PIX * DIM];   // fp16 z, pixel-major
__device__ __half g_Eh[(size_t)N_CODES * DIM]; // fp16 e, code-major
__device__ float  g_Zte[(size_t)N_PIX * DIM];  // exact z, pixel-major
__device__ float  g_norm2[N_CODES];            // exact ||e||^2
__device__ int2   g_top2[N_PIX];

__device__ __forceinline__ uint32_t s2u(const void* p) {
    return (uint32_t)__cvta_generic_to_shared(p);
}
__device__ __forceinline__ void cpasync16(uint32_t dst, const void* src) {
    asm volatile("cp.async.cg.shared.global [%0], [%1], 16;" :: "r"(dst), "l"(src));
}
__device__ __forceinline__ void ldsm4(uint32_t* r, uint32_t addr) {
    asm volatile("ldmatrix.sync.aligned.m8n8.x4.shared.b16 {%0,%1,%2,%3}, [%4];"
                 : "=r"(r[0]), "=r"(r[1]), "=r"(r[2]), "=r"(r[3]) : "r"(addr));
}
__device__ __forceinline__ void mma_f16(float* c, const uint32_t* a,
                                        const uint32_t* b) {
    asm volatile(
        "mma.sync.aligned.m16n8k16.row.col.f32.f16.f16.f32 "
        "{%0,%1,%2,%3},{%4,%5,%6,%7},{%8,%9},{%0,%1,%2,%3};"
        : "+f"(c[0]), "+f"(c[1]), "+f"(c[2]), "+f"(c[3])
        : "r"(a[0]), "r"(a[1]), "r"(a[2]), "r"(a[3]), "r"(b[0]), "r"(b[1]));
}

// ---------------------------------------------------------------------------
__global__ void prep_e_kernel(const float* __restrict__ emb) {
    int code = blockIdx.x * 8 + (threadIdx.x >> 5);
    int lane = threadIdx.x & 31;
    const float* src = emb + (size_t)code * DIM + lane * 8;
    __half* row = g_Eh + (size_t)code * DIM;
    float en = 0.f;
#pragma unroll
    for (int t = 0; t < 8; t++) {
        float v = src[t];
        en += v * v;
        row[lane * 8 + t] = __float2half_rn(v);
    }
#pragma unroll
    for (int o = 16; o > 0; o >>= 1) en += __shfl_xor_sync(0xffffffffu, en, o);
    if (lane == 0) g_norm2[code] = en;
}

__global__ void prep_z_kernel(const float* __restrict__ z) {
    __shared__ float Zs[DIM][33];
    int tid = threadIdx.x, lane = tid & 31, wid = tid >> 5;
    int px0 = blockIdx.x * 32;
    int b = px0 >> 10, hw0 = px0 & (HW - 1);
    for (int i = tid; i < DIM * 32; i += 256) {
        int d = i >> 5, px = i & 31;
        Zs[d][px] = z[((size_t)b * DIM + d) * HW + hw0 + px];
    }
    __syncthreads();
#pragma unroll
    for (int pp = 0; pp < 4; pp++) {
        int px = wid + pp * 8;
        __half* rowH = g_Zh + (size_t)(px0 + px) * DIM;
        float* rowE = g_Zte + (size_t)(px0 + px) * DIM;
#pragma unroll
        for (int i = 0; i < 8; i++) {
            int d = lane + 32 * i;
            float v = Zs[d][px];
            rowH[d] = __float2half_rn(v);
            rowE[d] = v;
        }
    }
}

// ---------------------------------------------------------------------------
// Main GEMM: CTA = 64 px x 256-code tiles; warp 32x64 fp16 m16n8k16;
// ldmatrix fragments, 2-stage cp.async, 1 sync/chunk; top-2 fold per tile.
// ---------------------------------------------------------------------------
__global__ void __launch_bounds__(GT, 2)
vq_gemm_kernel() {
    extern __shared__ char dsm[];
    __half* As = (__half*)dsm;
    char* Bs = dsm + A_BYTES;
    float* Ns = (float*)(dsm + NS_OFF);

    const int tid = threadIdx.x;
    const int lane = tid & 31;
    const int wid = tid >> 5;
    const int mw = wid >> 2;          // 0..1
    const int nw = wid & 3;           // 0..3
    const int g = lane >> 2;
    const int tig = lane & 3;
    const int p0 = blockIdx.x * PX_CTA;

    // ---- prologue: A panel (64 x 256 f16) ----
    {
        int r = tid >> 2, q = tid & 3;
        const __half* src = g_Zh + (size_t)(p0 + r) * DIM + q * 64;
        uint32_t dst = s2u(As + r * ASTR + q * 64);
#pragma unroll
        for (int j = 0; j < 8; j++) cpasync16(dst + j * 16, src + j * 8);
    }
    // ---- issue chunk 0 + norms 0 ----
    {
        const __half* src = g_Eh + (size_t)tid * DIM;
        uint32_t dst = s2u(Bs + tid * (BSTR * 2));
#pragma unroll
        for (int j = 0; j < 8; j++) cpasync16(dst + j * 16, src + j * 8);
        if (tid < 64) cpasync16(s2u(Ns + tid * 4), g_norm2 + tid * 4);
    }
    asm volatile("cp.async.commit_group;" ::: "memory");

    float acc[2][8][4];
#pragma unroll
    for (int mt = 0; mt < 2; mt++)
#pragma unroll
        for (int nt = 0; nt < 8; nt++)
#pragma unroll
            for (int r = 0; r < 4; r++) acc[mt][nt][r] = 0.f;

    float v1[4], v2[4];
    int i1[4], i2[4];
#pragma unroll
    for (int s = 0; s < 4; s++) { v1[s] = v2[s] = -3.4e38f; i1[s] = 0; i2[s] = 1; }

    // ldmatrix lane-address components (constant per thread)
    const int a_row_l = (lane & 7) + ((lane >> 3) & 1) * 8;
    const int a_col_l = (lane >> 4) * 8;
    const int b_row_l = ((lane >> 4) & 1) * 8 + (lane & 7);
    const int b_col_l = ((lane >> 3) & 1) * 8;

    for (int cc = 0; cc < NCHUNKS; cc++) {
        asm volatile("cp.async.wait_group 0;" ::: "memory");
        __syncthreads();

        // issue chunk cc+1
        if (cc + 1 < NCHUNKS) {
            const int nx = cc + 1;
            const int tn = nx >> 2, kn = nx & 3;
            const __half* src =
                g_Eh + (size_t)(tn * NTILE + tid) * DIM + kn * KC;
            uint32_t dst = s2u(Bs + (nx & 1) * BSTAGE_BYTES + tid * (BSTR * 2));
#pragma unroll
            for (int j = 0; j < 8; j++) cpasync16(dst + j * 16, src + j * 8);
            if (kn == 0 && tid < 64)
                cpasync16(s2u(Ns + (tn & 1) * NTILE + tid * 4),
                          g_norm2 + tn * NTILE + tid * 4);
        }
        asm volatile("cp.async.commit_group;" ::: "memory");

        // compute chunk cc (4 x k16 steps); A needs this chunk's K offset
        const char* sb = Bs + (cc & 1) * BSTAGE_BYTES;
        const int kb0 = (cc & 3) * KC;           // <-- round-4 bug fix
#pragma unroll
        for (int s = 0; s < 4; s++) {
            uint32_t a[2][4];
#pragma unroll
            for (int mt = 0; mt < 2; mt++) {
                uint32_t addr = s2u(As + (mw * 32 + mt * 16 + a_row_l) * ASTR +
                                    kb0 + s * 16 + a_col_l);
                ldsm4(a[mt], addr);
            }
            uint32_t b[8][2];
#pragma unroll
            for (int np = 0; np < 4; np++) {
                uint32_t r[4];
                uint32_t addr = s2u(sb + (nw * 64 + np * 16 + b_row_l) *
                                    (BSTR * 2) + (s * 16 + b_col_l) * 2);
                ldsm4(r, addr);
                b[2 * np][0] = r[0]; b[2 * np][1] = r[1];
                b[2 * np + 1][0] = r[2]; b[2 * np + 1][1] = r[3];
            }
#pragma unroll
            for (int mt = 0; mt < 2; mt++)
#pragma unroll
                for (int nt = 0; nt < 8; nt++)
                    mma_f16(acc[mt][nt], a[mt], b[nt]);
        }

        // fold tile
        if ((cc & 3) == 3) {
            const int t = cc >> 2;
            const float2* nsp = (const float2*)(Ns + (t & 1) * NTILE);
#pragma unroll
            for (int nt = 0; nt < 8; nt++) {
                float2 nn = nsp[nw * 32 + nt * 4 + tig];
                const int c0 = t * NTILE + nw * 64 + nt * 8 + 2 * tig;
#pragma unroll
                for (int mt = 0; mt < 2; mt++) {
                    float s0 = acc[mt][nt][0] - 0.5f * nn.x;
                    float s1 = acc[mt][nt][1] - 0.5f * nn.y;
                    float s2 = acc[mt][nt][2] - 0.5f * nn.x;
                    float s3 = acc[mt][nt][3] - 0.5f * nn.y;
                    int sa = mt * 2, sb2 = mt * 2 + 1;
                    if (s0 > v1[sa]) { v2[sa]=v1[sa]; i2[sa]=i1[sa]; v1[sa]=s0; i1[sa]=c0; }
                    else if (s0 > v2[sa]) { v2[sa]=s0; i2[sa]=c0; }
                    if (s1 > v1[sa]) { v2[sa]=v1[sa]; i2[sa]=i1[sa]; v1[sa]=s1; i1[sa]=c0+1; }
                    else if (s1 > v2[sa]) { v2[sa]=s1; i2[sa]=c0+1; }
                    if (s2 > v1[sb2]) { v2[sb2]=v1[sb2]; i2[sb2]=i1[sb2]; v1[sb2]=s2; i1[sb2]=c0; }
                    else if (s2 > v2[sb2]) { v2[sb2]=s2; i2[sb2]=c0; }
                    if (s3 > v1[sb2]) { v2[sb2]=v1[sb2]; i2[sb2]=i1[sb2]; v1[sb2]=s3; i1[sb2]=c0+1; }
                    else if (s3 > v2[sb2]) { v2[sb2]=s3; i2[sb2]=c0+1; }
                    acc[mt][nt][0] = acc[mt][nt][1] = 0.f;
                    acc[mt][nt][2] = acc[mt][nt][3] = 0.f;
                }
            }
        }
    }

    // ---- cross-thread top-2 reduce ----
    __syncthreads();
    float4* red = (float4*)dsm;      // [64 px][16 contributors]
#pragma unroll
    for (int s = 0; s < 4; s++) {
        int mt = s >> 1, h = s & 1;
        int pxl = mw * 32 + mt * 16 + h * 8 + g;
        red[pxl * 16 + nw * 4 + tig] =
            make_float4(v1[s], __int_as_float(i1[s]),
                        v2[s], __int_as_float(i2[s]));
    }
    __syncthreads();
    if (tid < PX_CTA) {
        float bv1 = -3.4e38f, bv2 = -3.4e38f;
        int bi1 = 0, bi2 = 1;
#pragma unroll
        for (int c = 0; c < 16; c++) {
            float4 e = red[tid * 16 + c];
#pragma unroll
            for (int h = 0; h < 2; h++) {
                float v = h ? e.z : e.x;
                int idx = __float_as_int(h ? e.w : e.y);
                if (v > bv1 || (v == bv1 && idx < bi1)) {
                    bv2 = bv1; bi2 = bi1; bv1 = v; bi1 = idx;
                } else if (v > bv2) { bv2 = v; bi2 = idx; }
            }
        }
        g_top2[p0 + tid] = make_int2(bi1, bi2);
    }
}

// ---------------------------------------------------------------------------
// Exact rescore of top-2 + gather + outputs.
// ---------------------------------------------------------------------------
__global__ void __launch_bounds__(256)
rescore_gather_kernel(const float* __restrict__ emb, float* __restrict__ out) {
    __shared__ int sel[PX_CTA];
    const int tid = threadIdx.x, lane = tid & 31, wid = tid >> 5;
    const int p0 = blockIdx.x * PX_CTA;

#pragma unroll 1
    for (int j = 0; j < 8; j++) {
        const int pxl = wid * 8 + j;
        const int px = p0 + pxl;
        const int2 cand = g_top2[px];
        const float4* zp = (const float4*)(g_Zte + (size_t)px * DIM);
        const float4* e1 = (const float4*)(emb + (size_t)cand.x * DIM);
        const float4* e2 = (const float4*)(emb + (size_t)cand.y * DIM);
        float d1 = 0.f, d2 = 0.f;
#pragma unroll
        for (int t = 0; t < 2; t++) {
            float4 zv = zp[lane + 32 * t];
            float4 a = e1[lane + 32 * t];
            float4 b = e2[lane + 32 * t];
            d1 += zv.x * a.x + zv.y * a.y + zv.z * a.z + zv.w * a.w;
            d2 += zv.x * b.x + zv.y * b.y + zv.z * b.z + zv.w * b.w;
        }
#pragma unroll
        for (int o = 16; o > 0; o >>= 1) {
            d1 += __shfl_xor_sync(0xffffffffu, d1, o);
            d2 += __shfl_xor_sync(0xffffffffu, d2, o);
        }
        if (lane == 0) {
            float s1 = d1 - 0.5f * g_norm2[cand.x];
            float s2 = d2 - 0.5f * g_norm2[cand.y];
            int best;
            if (s1 > s2) best = cand.x;
            else if (s2 > s1) best = cand.y;
            else best = min(cand.x, cand.y);
            sel[pxl] = best;
            out[IDX_OFF + px] = (float)best;
        }
    }
    __syncthreads();

    const int b = p0 >> 10;
    const int hw0 = p0 & (HW - 1);
    for (int i = tid; i < DIM * PX_CTA; i += 256) {
        int d = i >> 6, pxl = i & 63;
        out[((size_t)b * DIM + d) * HW + hw0 + pxl] =
            emb[(size_t)sel[pxl] * DIM + d];
    }
    if (blockIdx.x == 0 && tid == 0) out[LOSS_OFF] = 0.f;
}

// ---------------------------------------------------------------------------
extern "C" void kernel_launch(void* const* d_in, const int* in_sizes, int n_in,
                              void* d_out, int out_size) {
    const float* z = (const float*)d_in[0];
    const float* emb = (const float*)d_in[1];
    float* out = (float*)d_out;
    (void)in_sizes; (void)n_in; (void)out_size;

    static bool attr_set = false;
    if (!attr_set) {
        cudaFuncSetAttribute(vq_gemm_kernel,
                             cudaFuncAttributeMaxDynamicSharedMemorySize,
                             DYN_BYTES);
        attr_set = true;
    }

    prep_z_kernel<<<N_PIX / 32, 256>>>(z);
    prep_e_kernel<<<N_CODES / 8, 256>>>(emb);
    vq_gemm_kernel<<<N_PIX / PX_CTA, GT, DYN_BYTES>>>();
    rescore_gather_kernel<<<N_PIX / PX_CTA, 256>>>(emb, out);
}